// round 13
// baseline (speedup 1.0000x reference)
#include <cuda_runtime.h>
#include <cuda_bf16.h>
#include <cstdint>
#include <math.h>

#define BSZ 2
#define QLEN 1024
#define MLEN 1024
#define KLEN 2048
#define NH 16
#define DH 64
#define DM 1024

typedef __nv_bfloat16 bf16;
typedef __nv_bfloat162 bf162;

// ---------------- scratch ----------------
__device__ float g_q  [BSZ*QLEN*DM];
__device__ bf16 g_khi [BSZ*KLEN*DM];
__device__ bf16 g_klo [BSZ*KLEN*DM];
__device__ bf16 g_vhi [BSZ*KLEN*DM];
__device__ bf16 g_vlo [BSZ*KLEN*DM];
__device__ bf16 g_rhi [KLEN*DM];
__device__ bf16 g_rlo [KLEN*DM];
__device__ bf16 g_xhi [BSZ*QLEN*DM];
__device__ bf16 g_xlo [BSZ*QLEN*DM];
__device__ bf16 g_kihi[BSZ*KLEN*DM];
__device__ bf16 g_kilo[BSZ*KLEN*DM];
__device__ bf16 g_pohi[KLEN*DM];
__device__ bf16 g_polo[KLEN*DM];
__device__ bf16 g_whi [5*DM*DM];
__device__ bf16 g_wlo [5*DM*DM];
__device__ bf16 g_avhi[BSZ*QLEN*DM];
__device__ bf16 g_avlo[BSZ*QLEN*DM];
__device__ int  g_ctr;     // attention work counter
__device__ int  g_ctr2;    // projection GEMM work counter

// ---------------- helpers ----------------
__device__ __forceinline__ uint32_t smem_to_u32(const void* p) {
    uint32_t a;
    asm("{ .reg .u64 t; cvta.to.shared.u64 t, %1; cvt.u32.u64 %0, t; }" : "=r"(a) : "l"(p));
    return a;
}
#define CP_ASYNC16(dst, src) \
    asm volatile("cp.async.cg.shared.global [%0], [%1], 16;" :: "r"(dst), "l"(src) : "memory")
#define CP_COMMIT() asm volatile("cp.async.commit_group;" ::: "memory")
#define CP_WAIT1()  asm volatile("cp.async.wait_group 1;" ::: "memory")
#define CP_WAIT0()  asm volatile("cp.async.wait_group 0;" ::: "memory")

#define MMA_BF16(d, a, b) \
    asm volatile("mma.sync.aligned.m16n8k16.row.col.f32.bf16.bf16.f32 " \
        "{%0,%1,%2,%3}, {%4,%5,%6,%7}, {%8,%9}, {%0,%1,%2,%3};" \
        : "+f"((d)[0]), "+f"((d)[1]), "+f"((d)[2]), "+f"((d)[3]) \
        : "r"((a)[0]), "r"((a)[1]), "r"((a)[2]), "r"((a)[3]), \
          "r"((b)[0]), "r"((b)[1]))

#define LDMX4(r0, r1, r2, r3, addr) \
    asm volatile("ldmatrix.sync.aligned.m8n8.x4.shared.b16 {%0,%1,%2,%3}, [%4];" \
        : "=r"(r0), "=r"(r1), "=r"(r2), "=r"(r3) : "r"(addr))
#define LDMX4T(r0, r1, r2, r3, addr) \
    asm volatile("ldmatrix.sync.aligned.m8n8.x4.trans.shared.b16 {%0,%1,%2,%3}, [%4];" \
        : "=r"(r0), "=r"(r1), "=r"(r2), "=r"(r3) : "r"(addr))

__device__ __forceinline__ void split2(float a, float b, uint32_t& hi, uint32_t& lo) {
    bf162 h = __floats2bfloat162_rn(a, b);
    bf162 l = __floats2bfloat162_rn(a - __bfloat162float(h.x), b - __bfloat162float(h.y));
    hi = *reinterpret_cast<uint32_t*>(&h);
    lo = *reinterpret_cast<uint32_t*>(&l);
}

// ---------------- prep (fused): split x, pos, 5 weights, concat+split kin ----------------
#define XN4 (BSZ*QLEN*DM/4)
#define PN4 (KLEN*DM/4)
#define WN4 (DM*DM/4)
#define CN4 (BSZ*KLEN*DM/4)
#define PREP_TOT (XN4 + PN4 + 5*WN4 + CN4)

__global__ void prep_all(const float* __restrict__ x, const float* __restrict__ mem,
                         const float* __restrict__ pos,
                         const float* __restrict__ Wq, const float* __restrict__ Wk,
                         const float* __restrict__ Wv, const float* __restrict__ Wr,
                         const float* __restrict__ Wo) {
    int idx = blockIdx.x * blockDim.x + threadIdx.x;
    if (idx == 0) { g_ctr = 0; g_ctr2 = 0; }
    if (idx >= PREP_TOT) return;
    const int SPLIT_TOT = XN4 + PN4 + 5*WN4;
    if (idx < SPLIT_TOT) {
        const float* src; bf16 *hi, *lo; int base;
        if (idx < XN4)                { src = x;  hi = g_xhi; lo = g_xlo; base = 0; }
        else if (idx < XN4+PN4)       { src = pos; hi = g_pohi; lo = g_polo; base = XN4; }
        else if (idx < XN4+PN4+WN4)   { src = Wq; hi = g_whi;        lo = g_wlo;        base = XN4+PN4; }
        else if (idx < XN4+PN4+2*WN4) { src = Wk; hi = g_whi+DM*DM;  lo = g_wlo+DM*DM;  base = XN4+PN4+WN4; }
        else if (idx < XN4+PN4+3*WN4) { src = Wv; hi = g_whi+2*DM*DM; lo = g_wlo+2*DM*DM; base = XN4+PN4+2*WN4; }
        else if (idx < XN4+PN4+4*WN4) { src = Wr; hi = g_whi+3*DM*DM; lo = g_wlo+3*DM*DM; base = XN4+PN4+3*WN4; }
        else                          { src = Wo; hi = g_whi+4*DM*DM; lo = g_wlo+4*DM*DM; base = XN4+PN4+4*WN4; }
        int i = idx - base;
        float4 v = reinterpret_cast<const float4*>(src)[i];
        uint32_t h0, l0, h1, l1;
        split2(v.x, v.y, h0, l0);
        split2(v.z, v.w, h1, l1);
        reinterpret_cast<uint2*>(hi)[i] = make_uint2(h0, h1);
        reinterpret_cast<uint2*>(lo)[i] = make_uint2(l0, l1);
    } else {
        int i = idx - SPLIT_TOT;
        int e4   = i & (DM/4 - 1);
        int rest = i / (DM/4);
        int j = rest & (KLEN - 1);
        int b = rest >> 11;
        float4 v;
        if (j < MLEN) v = reinterpret_cast<const float4*>(mem)[(b*MLEN + j)*(DM/4) + e4];
        else          v = reinterpret_cast<const float4*>(x)[(b*QLEN + (j - MLEN))*(DM/4) + e4];
        uint32_t h0, l0, h1, l1;
        split2(v.x, v.y, h0, l0);
        split2(v.z, v.w, h1, l1);
        reinterpret_cast<uint2*>(g_kihi)[i] = make_uint2(h0, h1);
        reinterpret_cast<uint2*>(g_kilo)[i] = make_uint2(l0, l1);
    }
}

// ================= bf16 2-split GEMM body, templated on CTA M-rows =================
#define GBK 32
#define ROWB 40
#define GEMM_SMEMB (2*2*(128*ROWB + 128*ROWB)*2)   // MROWS=128 case: 81920 B

template<int MROWS>
__device__ __forceinline__ void gemm_body_t(
    const bf16* __restrict__ Ahi, const bf16* __restrict__ Alo,
    const bf16* __restrict__ Bhi, const bf16* __restrict__ Blo,
    float* __restrict__ C, bf16* __restrict__ Chi, bf16* __restrict__ Clo,
    int m0, int n0, int N, int K)
{
    constexpr int ATILE = MROWS*ROWB;
    constexpr int BTILE = 128*ROWB;
    constexpr int STG = 2*(ATILE + BTILE);
    constexpr int TOTCH = (2*MROWS + 256) * 4;
    constexpr int MT = MROWS/32;
    extern __shared__ bf16 sb[];
    const int tid = threadIdx.x;
    const int wid = tid >> 5, lane = tid & 31;
    const int wm = (wid >> 2) * (MROWS/2), wn = (wid & 3) * 32;
    const int r = lane >> 2, c = lane & 3;
    const uint32_t sbase = smem_to_u32(sb);

    float acc[MT][4][4];
    #pragma unroll
    for (int i = 0; i < MT; i++)
        #pragma unroll
        for (int j = 0; j < 4; j++)
            #pragma unroll
            for (int q = 0; q < 4; q++) acc[i][j][q] = 0.f;

    const bf16* mats[4] = { Ahi + (size_t)m0*K, Alo + (size_t)m0*K,
                            Bhi + (size_t)n0*K, Blo + (size_t)n0*K };

    auto g_issue = [&](int kt) {
        int st = kt & 1, k0 = kt * GBK;
        #pragma unroll
        for (int i = 0; i < TOTCH/256; i++) {
            int id = i*256 + tid;
            int mat, within, moff;
            if (id < 4*MROWS)          { mat = 0; within = id;                moff = 0; }
            else if (id < 8*MROWS)     { mat = 1; within = id - 4*MROWS;      moff = ATILE; }
            else if (id < 8*MROWS+512) { mat = 2; within = id - 8*MROWS;      moff = 2*ATILE; }
            else                       { mat = 3; within = id - 8*MROWS - 512; moff = 2*ATILE + BTILE; }
            int row = within >> 2, ch = within & 3;
            const bf16* src = mats[mat] + (size_t)row*K + k0 + ch*8;
            uint32_t dst = sbase + (uint32_t)(st*STG + moff + row*ROWB + ch*8)*2;
            CP_ASYNC16(dst, src);
        }
    };

    const int nK = K / GBK;
    g_issue(0); CP_COMMIT();

    const int aRow = lane & 15, aColOff = (lane >> 4) << 3;
    const int bRow = lane & 7, bColOff = ((lane >> 3) & 1) << 3, bBlk = lane >> 4;

    for (int kt = 0; kt < nK; kt++) {
        if (kt + 1 < nK) { g_issue(kt + 1); CP_COMMIT(); CP_WAIT1(); }
        else             { CP_WAIT0(); }
        __syncthreads();

        uint32_t Sb = sbase + (uint32_t)((kt & 1) * STG) * 2;
        uint32_t Ah = Sb, Al = Sb + ATILE*2, Bh = Sb + 2*ATILE*2, Bl = Sb + (2*ATILE + BTILE)*2;

        #pragma unroll
        for (int k16 = 0; k16 < GBK; k16 += 16) {
            uint32_t ah[MT][4], al[MT][4], bh[4][2], bl[4][2];
            #pragma unroll
            for (int mt = 0; mt < MT; mt++) {
                uint32_t off = (uint32_t)((wm + mt*16 + aRow)*ROWB + k16 + aColOff) * 2;
                LDMX4(ah[mt][0], ah[mt][1], ah[mt][2], ah[mt][3], Ah + off);
                LDMX4(al[mt][0], al[mt][1], al[mt][2], al[mt][3], Al + off);
            }
            #pragma unroll
            for (int p = 0; p < 2; p++) {
                uint32_t off = (uint32_t)((wn + (2*p + bBlk)*8 + bRow)*ROWB + k16 + bColOff) * 2;
                LDMX4(bh[2*p][0], bh[2*p][1], bh[2*p+1][0], bh[2*p+1][1], Bh + off);
                LDMX4(bl[2*p][0], bl[2*p][1], bl[2*p+1][0], bl[2*p+1][1], Bl + off);
            }
            #pragma unroll
            for (int mt = 0; mt < MT; mt++)
                #pragma unroll
                for (int nt = 0; nt < 4; nt++)
                    MMA_BF16(acc[mt][nt], ah[mt], bh[nt]);
            #pragma unroll
            for (int mt = 0; mt < MT; mt++)
                #pragma unroll
                for (int nt = 0; nt < 4; nt++)
                    MMA_BF16(acc[mt][nt], ah[mt], bl[nt]);
            #pragma unroll
            for (int mt = 0; mt < MT; mt++)
                #pragma unroll
                for (int nt = 0; nt < 4; nt++)
                    MMA_BF16(acc[mt][nt], al[mt], bh[nt]);
        }
        __syncthreads();
    }
    if (Chi) {
        #pragma unroll
        for (int mt = 0; mt < MT; mt++) {
            int row = m0 + wm + mt*16 + r;
            #pragma unroll
            for (int nt = 0; nt < 4; nt++) {
                int col = n0 + wn + nt*8 + 2*c;
                uint32_t h, l;
                split2(acc[mt][nt][0], acc[mt][nt][1], h, l);
                *(uint32_t*)&Chi[(size_t)row*N + col] = h;
                *(uint32_t*)&Clo[(size_t)row*N + col] = l;
                split2(acc[mt][nt][2], acc[mt][nt][3], h, l);
                *(uint32_t*)&Chi[(size_t)(row+8)*N + col] = h;
                *(uint32_t*)&Clo[(size_t)(row+8)*N + col] = l;
            }
        }
    } else {
        #pragma unroll
        for (int mt = 0; mt < MT; mt++) {
            int row = m0 + wm + mt*16 + r;
            #pragma unroll
            for (int nt = 0; nt < 4; nt++) {
                int col = n0 + wn + nt*8 + 2*c;
                *reinterpret_cast<float2*>(&C[(size_t)row*N + col]) = make_float2(acc[mt][nt][0], acc[mt][nt][1]);
                *reinterpret_cast<float2*>(&C[(size_t)(row+8)*N + col]) = make_float2(acc[mt][nt][2], acc[mt][nt][3]);
            }
        }
    }
}

// persistent fused projection GEMMs: 768 tiles (q 128 | k 256 | v 256 | r 128)
__global__ __launch_bounds__(256, 2) void gemm_proj4() {
    __shared__ int s_t;
    const int WN = DM*DM;
    for (;;) {
        __syncthreads();
        if (threadIdx.x == 0) s_t = atomicAdd(&g_ctr2, 1);
        __syncthreads();
        int t = s_t;
        if (t >= 768) return;
        int n0 = (t & 7) * 128;
        int y = t >> 3;
        if (y < 16)
            gemm_body_t<128>(g_xhi, g_xlo, g_whi, g_wlo, g_q, nullptr, nullptr, y*128, n0, DM, DM);
        else if (y < 48)
            gemm_body_t<128>(g_kihi, g_kilo, g_whi+WN, g_wlo+WN, nullptr, g_khi, g_klo, (y-16)*128, n0, DM, DM);
        else if (y < 80)
            gemm_body_t<128>(g_kihi, g_kilo, g_whi+2*WN, g_wlo+2*WN, nullptr, g_vhi, g_vlo, (y-48)*128, n0, DM, DM);
        else
            gemm_body_t<128>(g_pohi, g_polo, g_whi+3*WN, g_wlo+3*WN, nullptr, g_rhi, g_rlo, (y-80)*128, n0, DM, DM);
    }
}

// output GEMM: 64x128 tiles -> 256 CTAs = one full wave
__global__ __launch_bounds__(256, 2) void gemm_out(
    const bf16* __restrict__ Ahi, const bf16* __restrict__ Alo,
    const bf16* __restrict__ Bhi, const bf16* __restrict__ Blo,
    float* __restrict__ C, int M, int N, int K)
{
    gemm_body_t<64>(Ahi, Alo, Bhi, Blo, C, nullptr, nullptr, blockIdx.y*64, blockIdx.x*128, N, K);
}

// ================= persistent tensor-core flash attention (P in registers) =================
#define ST 72
#define TB 9216
#define O_QU 0
#define O_KH (4*TB)
#define O_KL (6*TB)
#define O_VH (8*TB)
#define O_VL (10*TB)
#define O_RH (12*TB)
#define O_RL (14*TB)
#define O_BD (16*TB)
#define BDS 66
#define O_ST (O_BD + 2*64*BDS*4)
#define ATT_SMEM (O_ST + 1024)
#define REDS 66
#define NITEMS 512

__global__ __launch_bounds__(256, 1) void attn_mma_kernel(
    const float* __restrict__ r_w_bias, const float* __restrict__ r_r_bias)
{
    extern __shared__ char smc[];
    const uint32_t sb = smem_to_u32(smc);
    float* bds  = (float*)(smc + O_BD);
    float* mred = (float*)(smc + O_ST);
    float* lred = mred + 64;
    __shared__ int s_item;

    const int tid = threadIdx.x;
    const int w = tid >> 5, lane = tid & 31;
    const int mt = w & 3, jh = w >> 2;
    const int r = lane >> 2, c = lane & 3;
    const int lrow = tid >> 2;
    const int dseg = (tid & 3) * 16;
    const int aro = mt*16, bro = jh*32;
    const int aRow = lane & 15, aColOff = (lane >> 4) << 3;
    const int bRow = lane & 7, bHalf = (lane >> 3) & 1, bBlk = lane >> 4;

    for (;;) {
        __syncthreads();
        if (tid == 0) s_item = atomicAdd(&g_ctr, 1);
        __syncthreads();
        const int item = s_item;
        if (item >= NITEMS) return;

        const int i0 = (15 - (item >> 5)) * 64;
        const int b = (item & 31) >> 4, hh = item & 15;
        const int relbase0 = 960 - i0;
        const int ntiles = i0/64 + 17;
        const size_t headoff = (size_t)hh*DH;

        #define CP_TILE(dstoff, gptr) do { \
            uint32_t _d = sb + (uint32_t)(dstoff) + (uint32_t)(lrow*ST + dseg)*2; \
            const bf16* _s = (gptr) + dseg; \
            CP_ASYNC16(_d, _s); CP_ASYNC16(_d + 16, _s + 8); \
        } while (0)
        #define ISSUE_KV(kt, bufi) do { \
            size_t _row = (size_t)(b*KLEN + (kt)*64 + lrow)*DM + headoff; \
            CP_TILE(O_KH + (bufi)*TB, g_khi + _row); \
            CP_TILE(O_KL + (bufi)*TB, g_klo + _row); \
            CP_TILE(O_VH + (bufi)*TB, g_vhi + _row); \
            CP_TILE(O_VL + (bufi)*TB, g_vlo + _row); \
        } while (0)
        #define ISSUE_RB(band, bufi) do { \
            int _rel = relbase0 + (band)*64 + lrow; \
            _rel = _rel < 0 ? 0 : (_rel > KLEN-1 ? KLEN-1 : _rel); \
            size_t _row = (size_t)_rel*DM + headoff; \
            CP_TILE(O_RH + (bufi)*TB, g_rhi + _row); \
            CP_TILE(O_RL + (bufi)*TB, g_rlo + _row); \
        } while (0)

        ISSUE_RB(0, 0); CP_COMMIT();
        ISSUE_RB(1, 1); ISSUE_KV(0, 0); CP_COMMIT();

        // ---- q prep into smem ----
        {
            const float* qrow = g_q + ((size_t)(b*QLEN + i0 + lrow))*DM + headoff + dseg;
            const float* ub = r_w_bias + headoff + dseg;
            const float* vb = r_r_bias + headoff + dseg;
            bf16* quhi = (bf16*)(smc + O_QU);
            bf16* qulo = (bf16*)(smc + O_QU + TB);
            bf16* qvhi = (bf16*)(smc + O_QU + 2*TB);
            bf16* qvlo = (bf16*)(smc + O_QU + 3*TB);
            #pragma unroll
            for (int p = 0; p < 4; p++) {
                float4 q4 = reinterpret_cast<const float4*>(qrow)[p];
                float4 u4 = reinterpret_cast<const float4*>(ub)[p];
                float4 v4 = reinterpret_cast<const float4*>(vb)[p];
                int dd = dseg + p*4;
                uint32_t h, l;
                split2((q4.x+u4.x)*0.125f, (q4.y+u4.y)*0.125f, h, l);
                *(uint32_t*)&quhi[lrow*ST+dd] = h; *(uint32_t*)&qulo[lrow*ST+dd] = l;
                split2((q4.z+u4.z)*0.125f, (q4.w+u4.w)*0.125f, h, l);
                *(uint32_t*)&quhi[lrow*ST+dd+2] = h; *(uint32_t*)&qulo[lrow*ST+dd+2] = l;
                split2((q4.x+v4.x)*0.125f, (q4.y+v4.y)*0.125f, h, l);
                *(uint32_t*)&qvhi[lrow*ST+dd] = h; *(uint32_t*)&qvlo[lrow*ST+dd] = l;
                split2((q4.z+v4.z)*0.125f, (q4.w+v4.w)*0.125f, h, l);
                *(uint32_t*)&qvhi[lrow*ST+dd+2] = h; *(uint32_t*)&qvlo[lrow*ST+dd+2] = l;
            }
        }
        CP_WAIT1();
        __syncthreads();

        // ---- preload q fragments ----
        uint32_t quh[4][4], qul[4][4], qvh[4][4], qvl[4][4];
        #pragma unroll
        for (int kc = 0; kc < 4; kc++) {
            uint32_t aoff = (uint32_t)((aro + aRow)*ST + kc*16 + aColOff) * 2;
            LDMX4(quh[kc][0], quh[kc][1], quh[kc][2], quh[kc][3], sb + O_QU + aoff);
            LDMX4(qul[kc][0], qul[kc][1], qul[kc][2], qul[kc][3], sb + O_QU + TB + aoff);
            LDMX4(qvh[kc][0], qvh[kc][1], qvh[kc][2], qvh[kc][3], sb + O_QU + 2*TB + aoff);
            LDMX4(qvl[kc][0], qvl[kc][1], qvl[kc][2], qvl[kc][3], sb + O_QU + 3*TB + aoff);
        }

        #define LOADB_NK(BH, BL, kcv, BHbase, BLbase) do { \
            _Pragma("unroll") \
            for (int p = 0; p < 2; p++) { \
                uint32_t boff = (uint32_t)((bro + (2*p + bBlk)*8 + bRow)*ST + (kcv)*16 + bHalf*8) * 2; \
                LDMX4(BH[2*p][0], BH[2*p][1], BH[2*p+1][0], BH[2*p+1][1], (BHbase) + boff); \
                LDMX4(BL[2*p][0], BL[2*p][1], BL[2*p+1][0], BL[2*p+1][1], (BLbase) + boff); \
            } \
        } while (0)

        #define GEMM_NK(ACC, AH, AL, BHbase, BLbase) do { \
            uint32_t bhf[2][4][2], blf[2][4][2]; \
            LOADB_NK(bhf[0], blf[0], 0, BHbase, BLbase); \
            _Pragma("unroll") \
            for (int kc = 0; kc < 4; kc++) { \
                int cur = kc & 1; \
                if (kc < 3) LOADB_NK(bhf[cur^1], blf[cur^1], kc+1, BHbase, BLbase); \
                _Pragma("unroll") \
                for (int nt = 0; nt < 4; nt++) \
                    MMA_BF16(ACC[nt], AH[kc], bhf[cur][nt]); \
                _Pragma("unroll") \
                for (int nt = 0; nt < 4; nt++) \
                    MMA_BF16(ACC[nt], AH[kc], blf[cur][nt]); \
                _Pragma("unroll") \
                for (int nt = 0; nt < 4; nt++) \
                    MMA_BF16(ACC[nt], AL[kc], bhf[cur][nt]); \
            } \
        } while (0)

        #define BD_STORE(bda, bufidx) do { \
            float* bdw = bds + (bufidx) * 64 * BDS; \
            _Pragma("unroll") \
            for (int nt = 0; nt < 4; nt++) { \
                int tc = bro + nt*8 + 2*c; \
                *reinterpret_cast<float2*>(&bdw[(aro+r)*BDS + tc]) = make_float2(bda[nt][0], bda[nt][1]); \
                *reinterpret_cast<float2*>(&bdw[(aro+r+8)*BDS + tc]) = make_float2(bda[nt][2], bda[nt][3]); \
            } \
        } while (0)

        // ---- prologue BD bands 0,1 ----
        {
            float bda[4][4];
            #pragma unroll
            for (int nt = 0; nt < 4; nt++)
                #pragma unroll
                for (int q = 0; q < 4; q++) bda[nt][q] = 0.f;
            GEMM_NK(bda, qvh, qvl, sb + O_RH, sb + O_RL);
            BD_STORE(bda, 0);
        }
        __syncthreads();
        ISSUE_RB(2, 0); CP_COMMIT();
        CP_WAIT1();
        __syncthreads();
        {
            float bda[4][4];
            #pragma unroll
            for (int nt = 0; nt < 4; nt++)
                #pragma unroll
                for (int q = 0; q < 4; q++) bda[nt][q] = 0.f;
            GEMM_NK(bda, qvh, qvl, sb + O_RH + TB, sb + O_RL + TB);
            BD_STORE(bda, 1);
        }

        float out[8][4];
        #pragma unroll
        for (int nt = 0; nt < 8; nt++)
            #pragma unroll
            for (int q = 0; q < 4; q++) out[nt][q] = 0.f;
        float lsum0 = 0.f, lsum1 = 0.f, mrun0 = -1e4f, mrun1 = -1e4f;

        for (int kt = 0; kt < ntiles; kt++) {
            const int j0 = kt * 64;
            const int buf = kt & 1, nbuf = buf ^ 1;
            CP_WAIT0();
            __syncthreads();
            if (kt + 1 < ntiles) {
                ISSUE_KV(kt + 1, nbuf);
                ISSUE_RB(kt + 3, nbuf);
                CP_COMMIT();
            }

            // ---- AC ----
            float s[4][4];
            #pragma unroll
            for (int nt = 0; nt < 4; nt++)
                #pragma unroll
                for (int q = 0; q < 4; q++) s[nt][q] = 0.f;
            GEMM_NK(s, quh, qul, sb + O_KH + buf*TB, sb + O_KL + buf*TB);

            // ---- BD gather (mask hoisted to last tile) ----
            const float* bdLo = bds + buf * 64 * BDS;
            const float* bdHi = bds + nbuf * 64 * BDS;
            #pragma unroll
            for (int nt = 0; nt < 4; nt++)
                #pragma unroll
                for (int q = 0; q < 4; q++) {
                    int il = aro + r + ((q >= 2) ? 8 : 0);
                    int jl = bro + nt*8 + 2*c + (q & 1);
                    int t = jl - il + 63;
                    float bd = (t < 64) ? bdLo[il*BDS + t] : bdHi[il*BDS + t - 64];
                    s[nt][q] += bd;
                }
            if (kt == ntiles - 1) {
                // j0 - i0 == MLEN here: mask is jl > il
                #pragma unroll
                for (int nt = 0; nt < 4; nt++)
                    #pragma unroll
                    for (int q = 0; q < 4; q++) {
                        int il = aro + r + ((q >= 2) ? 8 : 0);
                        int jl = bro + nt*8 + 2*c + (q & 1);
                        if (jl > il) s[nt][q] = -1e30f;
                    }
            }

            // ---- pair barrier + next BD band ----
            if (kt + 1 < ntiles) {
                asm volatile("bar.sync %0, 64;" :: "r"(1 + mt) : "memory");
                float bda[4][4];
                #pragma unroll
                for (int nt = 0; nt < 4; nt++)
                    #pragma unroll
                    for (int q = 0; q < 4; q++) bda[nt][q] = 0.f;
                GEMM_NK(bda, qvh, qvl, sb + O_RH + buf*TB, sb + O_RL + buf*TB);
                BD_STORE(bda, buf);
            }

            // ---- per-half online softmax ----
            float pmax0 = -1e30f, pmax1 = -1e30f;
            #pragma unroll
            for (int nt = 0; nt < 4; nt++) {
                pmax0 = fmaxf(pmax0, fmaxf(s[nt][0], s[nt][1]));
                pmax1 = fmaxf(pmax1, fmaxf(s[nt][2], s[nt][3]));
            }
            pmax0 = fmaxf(pmax0, __shfl_xor_sync(~0u, pmax0, 1));
            pmax0 = fmaxf(pmax0, __shfl_xor_sync(~0u, pmax0, 2));
            pmax1 = fmaxf(pmax1, __shfl_xor_sync(~0u, pmax1, 1));
            pmax1 = fmaxf(pmax1, __shfl_xor_sync(~0u, pmax1, 2));
            float mn0 = fmaxf(mrun0, pmax0), mn1 = fmaxf(mrun1, pmax1);
            float ps0 = 0.f, ps1 = 0.f;
            #pragma unroll
            for (int nt = 0; nt < 4; nt++) {
                s[nt][0] = __expf(s[nt][0] - mn0);
                s[nt][1] = __expf(s[nt][1] - mn0);
                s[nt][2] = __expf(s[nt][2] - mn1);
                s[nt][3] = __expf(s[nt][3] - mn1);
                ps0 += s[nt][0] + s[nt][1];
                ps1 += s[nt][2] + s[nt][3];
            }
            ps0 += __shfl_xor_sync(~0u, ps0, 1); ps0 += __shfl_xor_sync(~0u, ps0, 2);
            ps1 += __shfl_xor_sync(~0u, ps1, 1); ps1 += __shfl_xor_sync(~0u, ps1, 2);
            float corr0 = __expf(mrun0 - mn0), corr1 = __expf(mrun1 - mn1);
            lsum0 = lsum0 * corr0 + ps0;
            lsum1 = lsum1 * corr1 + ps1;
            mrun0 = mn0; mrun1 = mn1;
            #pragma unroll
            for (int nt = 0; nt < 8; nt++) {
                out[nt][0] *= corr0; out[nt][1] *= corr0;
                out[nt][2] *= corr1; out[nt][3] *= corr1;
            }

            // ---- pack P A-frags ----
            uint32_t pah[2][4], pal[2][4];
            #pragma unroll
            for (int kc = 0; kc < 2; kc++) {
                split2(s[2*kc][0],   s[2*kc][1],   pah[kc][0], pal[kc][0]);
                split2(s[2*kc][2],   s[2*kc][3],   pah[kc][1], pal[kc][1]);
                split2(s[2*kc+1][0], s[2*kc+1][1], pah[kc][2], pal[kc][2]);
                split2(s[2*kc+1][2], s[2*kc+1][3], pah[kc][3], pal[kc][3]);
            }

            // ---- PV ----
            {
                uint32_t VH = sb + O_VH + buf*TB, VL = sb + O_VL + buf*TB;
                uint32_t vhf[2][8][2], vlf[2][8][2];
                #define LOADV(slot, kcv) do { \
                    int co = jh*32 + (kcv)*16; \
                    _Pragma("unroll") \
                    for (int p = 0; p < 4; p++) { \
                        uint32_t boff = (uint32_t)((co + bRow + bHalf*8)*ST + (2*p + bBlk)*8) * 2; \
                        LDMX4T(vhf[slot][2*p][0], vhf[slot][2*p][1], vhf[slot][2*p+1][0], vhf[slot][2*p+1][1], VH + boff); \
                        LDMX4T(vlf[slot][2*p][0], vlf[slot][2*p][1], vlf[slot][2*p+1][0], vlf[slot][2*p+1][1], VL + boff); \
                    } \
                } while (0)
                LOADV(0, 0);
                #pragma unroll
                for (int kc = 0; kc < 2; kc++) {
                    if (kc == 0) LOADV(1, 1);
                    #pragma unroll
                    for (int nt = 0; nt < 8; nt++)
                        MMA_BF16(out[nt], pah[kc], vhf[kc][nt]);
                    #pragma unroll
                    for (int nt = 0; nt < 8; nt++)
                        MMA_BF16(out[nt], pah[kc], vlf[kc][nt]);
                    #pragma unroll
                    for (int nt = 0; nt < 8; nt++)
                        MMA_BF16(out[nt], pal[kc], vhf[kc][nt]);
                }
                #undef LOADV
            }
        }

        // ---- combine jh halves ----
        float* red = bds;
        __syncthreads();
        if (jh == 0) {
            #pragma unroll
            for (int nt = 0; nt < 8; nt++) {
                int col = nt*8 + 2*c;
                *reinterpret_cast<float2*>(&red[(aro+r)*REDS + col])   = make_float2(out[nt][0], out[nt][1]);
                *reinterpret_cast<float2*>(&red[(aro+r+8)*REDS + col]) = make_float2(out[nt][2], out[nt][3]);
            }
            if (c == 0) {
                mred[aro+r] = mrun0;   mred[aro+r+8] = mrun1;
                lred[aro+r] = lsum0;   lred[aro+r+8] = lsum1;
            }
        }
        __syncthreads();
        if (jh == 1) {
            float mA0 = mred[aro+r],   lA0 = lred[aro+r];
            float mA1 = mred[aro+r+8], lA1 = lred[aro+r+8];
            float M0 = fmaxf(mA0, mrun0), M1 = fmaxf(mA1, mrun1);
            float eA0 = __expf(mA0 - M0), eB0 = __expf(mrun0 - M0);
            float eA1 = __expf(mA1 - M1), eB1 = __expf(mrun1 - M1);
            float inv0 = 1.f / (lA0*eA0 + lsum0*eB0);
            float inv1 = 1.f / (lA1*eA1 + lsum1*eB1);
            #pragma unroll
            for (int nt = 0; nt < 8; nt++) {
                int col = nt*8 + 2*c;
                float2 oA0 = *reinterpret_cast<float2*>(&red[(aro+r)*REDS + col]);
                float2 oA1 = *reinterpret_cast<float2*>(&red[(aro+r+8)*REDS + col]);
                float v0 = (oA0.x*eA0 + out[nt][0]*eB0) * inv0;
                float v1 = (oA0.y*eA0 + out[nt][1]*eB0) * inv0;
                float v2 = (oA1.x*eA1 + out[nt][2]*eB1) * inv1;
                float v3 = (oA1.y*eA1 + out[nt][3]*eB1) * inv1;
                size_t row0 = (size_t)(b*QLEN + i0 + aro + r) * DM + hh*DH + col;
                size_t row1 = row0 + 8*DM;
                uint32_t h, l;
                split2(v0, v1, h, l);
                *(uint32_t*)&g_avhi[row0] = h; *(uint32_t*)&g_avlo[row0] = l;
                split2(v2, v3, h, l);
                *(uint32_t*)&g_avhi[row1] = h; *(uint32_t*)&g_avlo[row1] = l;
            }
        }
    }
}

// ---------------- launch ----------------
extern "C" void kernel_launch(void* const* d_in, const int* in_sizes, int n_in,
                              void* d_out, int out_size)
{
    (void)in_sizes; (void)n_in; (void)out_size;
    const float* x   = (const float*)d_in[0];
    const float* mem = (const float*)d_in[1];
    const float* pos = (const float*)d_in[2];
    const float* Wq  = (const float*)d_in[4];
    const float* Wk  = (const float*)d_in[5];
    const float* Wv  = (const float*)d_in[6];
    const float* Wr  = (const float*)d_in[7];
    const float* Wo  = (const float*)d_in[8];
    const float* rwb = (const float*)d_in[9];
    const float* rrb = (const float*)d_in[10];
    float* out = (float*)d_out;

    bf16 *pwh, *pwl, *pavh, *pavl;
    cudaGetSymbolAddress((void**)&pwh,  g_whi);
    cudaGetSymbolAddress((void**)&pwl,  g_wlo);
    cudaGetSymbolAddress((void**)&pavh, g_avhi);
    cudaGetSymbolAddress((void**)&pavl, g_avlo);

    prep_all<<<(PREP_TOT + 255)/256, 256>>>(x, mem, pos, Wq, Wk, Wv, Wr, Wo);

    cudaFuncSetAttribute(gemm_proj4, cudaFuncAttributeMaxDynamicSharedMemorySize, GEMM_SMEMB);
    gemm_proj4<<<304, 256, GEMM_SMEMB>>>();

    cudaFuncSetAttribute(attn_mma_kernel, cudaFuncAttributeMaxDynamicSharedMemorySize, ATT_SMEM);
    attn_mma_kernel<<<152, 256, ATT_SMEM>>>(rwb, rrb);

    cudaFuncSetAttribute(gemm_out, cudaFuncAttributeMaxDynamicSharedMemorySize, GEMM_SMEMB);
    gemm_out<<<dim3(DM/128, BSZ*QLEN/64), 256, GEMM_SMEMB>>>(pavh, pavl, pwh+4*DM*DM, pwl+4*DM*DM, out, BSZ*QLEN, DM, DM);
}

// round 14
// speedup vs baseline: 1.0247x; 1.0247x over previous
#include <cuda_runtime.h>
#include <cuda_bf16.h>
#include <cstdint>
#include <math.h>

#define BSZ 2
#define QLEN 1024
#define MLEN 1024
#define KLEN 2048
#define NH 16
#define DH 64
#define DM 1024

typedef __nv_bfloat16 bf16;
typedef __nv_bfloat162 bf162;

// ---------------- scratch ----------------
__device__ float g_q  [BSZ*QLEN*DM];
__device__ bf16 g_khi [BSZ*KLEN*DM];
__device__ bf16 g_klo [BSZ*KLEN*DM];
__device__ bf16 g_vhi [BSZ*KLEN*DM];
__device__ bf16 g_vlo [BSZ*KLEN*DM];
__device__ bf16 g_rhi [KLEN*DM];
__device__ bf16 g_rlo [KLEN*DM];
__device__ bf16 g_xhi [BSZ*QLEN*DM];
__device__ bf16 g_xlo [BSZ*QLEN*DM];
__device__ bf16 g_kihi[BSZ*KLEN*DM];
__device__ bf16 g_kilo[BSZ*KLEN*DM];
__device__ bf16 g_pohi[KLEN*DM];
__device__ bf16 g_polo[KLEN*DM];
__device__ bf16 g_whi [5*DM*DM];
__device__ bf16 g_wlo [5*DM*DM];
__device__ bf16 g_avhi[BSZ*QLEN*DM];
__device__ bf16 g_avlo[BSZ*QLEN*DM];
__device__ int  g_ctr;     // attention work counter
__device__ int  g_ctr2;    // projection GEMM work counter

// ---------------- helpers ----------------
__device__ __forceinline__ uint32_t smem_to_u32(const void* p) {
    uint32_t a;
    asm("{ .reg .u64 t; cvta.to.shared.u64 t, %1; cvt.u32.u64 %0, t; }" : "=r"(a) : "l"(p));
    return a;
}
#define CP_ASYNC16(dst, src) \
    asm volatile("cp.async.cg.shared.global [%0], [%1], 16;" :: "r"(dst), "l"(src) : "memory")
#define CP_COMMIT() asm volatile("cp.async.commit_group;" ::: "memory")
#define CP_WAIT1()  asm volatile("cp.async.wait_group 1;" ::: "memory")
#define CP_WAIT0()  asm volatile("cp.async.wait_group 0;" ::: "memory")

#define MMA_BF16(d, a, b) \
    asm volatile("mma.sync.aligned.m16n8k16.row.col.f32.bf16.bf16.f32 " \
        "{%0,%1,%2,%3}, {%4,%5,%6,%7}, {%8,%9}, {%0,%1,%2,%3};" \
        : "+f"((d)[0]), "+f"((d)[1]), "+f"((d)[2]), "+f"((d)[3]) \
        : "r"((a)[0]), "r"((a)[1]), "r"((a)[2]), "r"((a)[3]), \
          "r"((b)[0]), "r"((b)[1]))

#define LDMX4(r0, r1, r2, r3, addr) \
    asm volatile("ldmatrix.sync.aligned.m8n8.x4.shared.b16 {%0,%1,%2,%3}, [%4];" \
        : "=r"(r0), "=r"(r1), "=r"(r2), "=r"(r3) : "r"(addr))
#define LDMX4T(r0, r1, r2, r3, addr) \
    asm volatile("ldmatrix.sync.aligned.m8n8.x4.trans.shared.b16 {%0,%1,%2,%3}, [%4];" \
        : "=r"(r0), "=r"(r1), "=r"(r2), "=r"(r3) : "r"(addr))

__device__ __forceinline__ void split2(float a, float b, uint32_t& hi, uint32_t& lo) {
    bf162 h = __floats2bfloat162_rn(a, b);
    bf162 l = __floats2bfloat162_rn(a - __bfloat162float(h.x), b - __bfloat162float(h.y));
    hi = *reinterpret_cast<uint32_t*>(&h);
    lo = *reinterpret_cast<uint32_t*>(&l);
}

// ---------------- prep (fused): split x, pos, 5 weights, concat+split kin ----------------
#define XN4 (BSZ*QLEN*DM/4)
#define PN4 (KLEN*DM/4)
#define WN4 (DM*DM/4)
#define CN4 (BSZ*KLEN*DM/4)
#define PREP_TOT (XN4 + PN4 + 5*WN4 + CN4)

__global__ void prep_all(const float* __restrict__ x, const float* __restrict__ mem,
                         const float* __restrict__ pos,
                         const float* __restrict__ Wq, const float* __restrict__ Wk,
                         const float* __restrict__ Wv, const float* __restrict__ Wr,
                         const float* __restrict__ Wo) {
    int idx = blockIdx.x * blockDim.x + threadIdx.x;
    if (idx == 0) { g_ctr = 0; g_ctr2 = 0; }
    if (idx >= PREP_TOT) return;
    const int SPLIT_TOT = XN4 + PN4 + 5*WN4;
    if (idx < SPLIT_TOT) {
        const float* src; bf16 *hi, *lo; int base;
        if (idx < XN4)                { src = x;  hi = g_xhi; lo = g_xlo; base = 0; }
        else if (idx < XN4+PN4)       { src = pos; hi = g_pohi; lo = g_polo; base = XN4; }
        else if (idx < XN4+PN4+WN4)   { src = Wq; hi = g_whi;        lo = g_wlo;        base = XN4+PN4; }
        else if (idx < XN4+PN4+2*WN4) { src = Wk; hi = g_whi+DM*DM;  lo = g_wlo+DM*DM;  base = XN4+PN4+WN4; }
        else if (idx < XN4+PN4+3*WN4) { src = Wv; hi = g_whi+2*DM*DM; lo = g_wlo+2*DM*DM; base = XN4+PN4+2*WN4; }
        else if (idx < XN4+PN4+4*WN4) { src = Wr; hi = g_whi+3*DM*DM; lo = g_wlo+3*DM*DM; base = XN4+PN4+3*WN4; }
        else                          { src = Wo; hi = g_whi+4*DM*DM; lo = g_wlo+4*DM*DM; base = XN4+PN4+4*WN4; }
        int i = idx - base;
        float4 v = reinterpret_cast<const float4*>(src)[i];
        uint32_t h0, l0, h1, l1;
        split2(v.x, v.y, h0, l0);
        split2(v.z, v.w, h1, l1);
        reinterpret_cast<uint2*>(hi)[i] = make_uint2(h0, h1);
        reinterpret_cast<uint2*>(lo)[i] = make_uint2(l0, l1);
    } else {
        int i = idx - SPLIT_TOT;
        int e4   = i & (DM/4 - 1);
        int rest = i / (DM/4);
        int j = rest & (KLEN - 1);
        int b = rest >> 11;
        float4 v;
        if (j < MLEN) v = reinterpret_cast<const float4*>(mem)[(b*MLEN + j)*(DM/4) + e4];
        else          v = reinterpret_cast<const float4*>(x)[(b*QLEN + (j - MLEN))*(DM/4) + e4];
        uint32_t h0, l0, h1, l1;
        split2(v.x, v.y, h0, l0);
        split2(v.z, v.w, h1, l1);
        reinterpret_cast<uint2*>(g_kihi)[i] = make_uint2(h0, h1);
        reinterpret_cast<uint2*>(g_kilo)[i] = make_uint2(l0, l1);
    }
}

// ================= bf16 2-split GEMM body (128x128 tiles, 2-stage, 2 CTAs/SM) =================
#define GBK 32
#define ROWB 40
#define TILEB (128*ROWB)
#define STGB (4*TILEB)
#define GEMM_SMEMB (2*STGB*2)

__device__ __forceinline__ void gemm_body(
    const bf16* __restrict__ Ahi, const bf16* __restrict__ Alo,
    const bf16* __restrict__ Bhi, const bf16* __restrict__ Blo,
    float* __restrict__ C, bf16* __restrict__ Chi, bf16* __restrict__ Clo,
    int m0, int n0, int N, int K)
{
    extern __shared__ bf16 sb[];
    const int tid = threadIdx.x;
    const int wid = tid >> 5, lane = tid & 31;
    const int wm = (wid >> 2) * 64, wn = (wid & 3) * 32;
    const int r = lane >> 2, c = lane & 3;
    const uint32_t sbase = smem_to_u32(sb);

    float acc[4][4][4];
    #pragma unroll
    for (int i = 0; i < 4; i++)
        #pragma unroll
        for (int j = 0; j < 4; j++)
            #pragma unroll
            for (int q = 0; q < 4; q++) acc[i][j][q] = 0.f;

    const bf16* mats[4] = { Ahi + (size_t)m0*K, Alo + (size_t)m0*K,
                            Bhi + (size_t)n0*K, Blo + (size_t)n0*K };
    int l_mat[8], l_row[8], l_ch[8];
    #pragma unroll
    for (int i = 0; i < 8; i++) {
        int id = i*256 + tid;
        l_mat[i] = id >> 9; l_row[i] = (id >> 2) & 127; l_ch[i] = id & 3;
    }

    #define G_ISSUE(kt) do { \
        int _s = (kt) & 1, _k0 = (kt) * GBK; \
        _Pragma("unroll") \
        for (int _i = 0; _i < 8; _i++) { \
            const bf16* _src = mats[l_mat[_i]] + (size_t)l_row[_i]*K + _k0 + l_ch[_i]*8; \
            uint32_t _dst = sbase + (uint32_t)(_s*STGB + l_mat[_i]*TILEB + l_row[_i]*ROWB + l_ch[_i]*8)*2; \
            CP_ASYNC16(_dst, _src); \
        } \
    } while (0)

    const int nK = K / GBK;
    G_ISSUE(0); CP_COMMIT();

    const int aRow = lane & 15, aColOff = (lane >> 4) << 3;
    const int bRow = lane & 7, bColOff = ((lane >> 3) & 1) << 3, bBlk = lane >> 4;

    for (int kt = 0; kt < nK; kt++) {
        if (kt + 1 < nK) { G_ISSUE(kt + 1); CP_COMMIT(); CP_WAIT1(); }
        else             { CP_WAIT0(); }
        __syncthreads();

        uint32_t Sb = sbase + (uint32_t)((kt & 1) * STGB) * 2;
        uint32_t Ah = Sb, Al = Sb + TILEB*2, Bh = Sb + 2*TILEB*2, Bl = Sb + 3*TILEB*2;

        #pragma unroll
        for (int k16 = 0; k16 < GBK; k16 += 16) {
            uint32_t ah[4][4], al[4][4], bh[4][2], bl[4][2];
            #pragma unroll
            for (int mt = 0; mt < 4; mt++) {
                uint32_t off = (uint32_t)((wm + mt*16 + aRow)*ROWB + k16 + aColOff) * 2;
                LDMX4(ah[mt][0], ah[mt][1], ah[mt][2], ah[mt][3], Ah + off);
                LDMX4(al[mt][0], al[mt][1], al[mt][2], al[mt][3], Al + off);
            }
            #pragma unroll
            for (int p = 0; p < 2; p++) {
                uint32_t off = (uint32_t)((wn + (2*p + bBlk)*8 + bRow)*ROWB + k16 + bColOff) * 2;
                LDMX4(bh[2*p][0], bh[2*p][1], bh[2*p+1][0], bh[2*p+1][1], Bh + off);
                LDMX4(bl[2*p][0], bl[2*p][1], bl[2*p+1][0], bl[2*p+1][1], Bl + off);
            }
            #pragma unroll
            for (int mt = 0; mt < 4; mt++)
                #pragma unroll
                for (int nt = 0; nt < 4; nt++)
                    MMA_BF16(acc[mt][nt], ah[mt], bh[nt]);
            #pragma unroll
            for (int mt = 0; mt < 4; mt++)
                #pragma unroll
                for (int nt = 0; nt < 4; nt++)
                    MMA_BF16(acc[mt][nt], ah[mt], bl[nt]);
            #pragma unroll
            for (int mt = 0; mt < 4; mt++)
                #pragma unroll
                for (int nt = 0; nt < 4; nt++)
                    MMA_BF16(acc[mt][nt], al[mt], bh[nt]);
        }
        __syncthreads();
    }
    if (Chi) {
        #pragma unroll
        for (int mt = 0; mt < 4; mt++) {
            int row = m0 + wm + mt*16 + r;
            #pragma unroll
            for (int nt = 0; nt < 4; nt++) {
                int col = n0 + wn + nt*8 + 2*c;
                uint32_t h, l;
                split2(acc[mt][nt][0], acc[mt][nt][1], h, l);
                *(uint32_t*)&Chi[(size_t)row*N + col] = h;
                *(uint32_t*)&Clo[(size_t)row*N + col] = l;
                split2(acc[mt][nt][2], acc[mt][nt][3], h, l);
                *(uint32_t*)&Chi[(size_t)(row+8)*N + col] = h;
                *(uint32_t*)&Clo[(size_t)(row+8)*N + col] = l;
            }
        }
    } else {
        #pragma unroll
        for (int mt = 0; mt < 4; mt++) {
            int row = m0 + wm + mt*16 + r;
            #pragma unroll
            for (int nt = 0; nt < 4; nt++) {
                int col = n0 + wn + nt*8 + 2*c;
                *reinterpret_cast<float2*>(&C[(size_t)row*N + col]) = make_float2(acc[mt][nt][0], acc[mt][nt][1]);
                *reinterpret_cast<float2*>(&C[(size_t)(row+8)*N + col]) = make_float2(acc[mt][nt][2], acc[mt][nt][3]);
            }
        }
    }
}

// persistent fused projection GEMMs: 768 tiles (q 128 | k 256 | v 256 | r 128)
__global__ __launch_bounds__(256, 2) void gemm_proj4() {
    __shared__ int s_t;
    const int WN = DM*DM;
    for (;;) {
        __syncthreads();
        if (threadIdx.x == 0) s_t = atomicAdd(&g_ctr2, 1);
        __syncthreads();
        int t = s_t;
        if (t >= 768) return;
        int n0 = (t & 7) * 128;
        int y = t >> 3;
        if (y < 16)
            gemm_body(g_xhi, g_xlo, g_whi, g_wlo, g_q, nullptr, nullptr, y*128, n0, DM, DM);
        else if (y < 48)
            gemm_body(g_kihi, g_kilo, g_whi+WN, g_wlo+WN, nullptr, g_khi, g_klo, (y-16)*128, n0, DM, DM);
        else if (y < 80)
            gemm_body(g_kihi, g_kilo, g_whi+2*WN, g_wlo+2*WN, nullptr, g_vhi, g_vlo, (y-48)*128, n0, DM, DM);
        else
            gemm_body(g_pohi, g_polo, g_whi+3*WN, g_wlo+3*WN, nullptr, g_rhi, g_rlo, (y-80)*128, n0, DM, DM);
    }
}

// output GEMM: 128x128 tiles (R12 configuration)
__global__ __launch_bounds__(256, 2) void gemm_out(
    const bf16* __restrict__ Ahi, const bf16* __restrict__ Alo,
    const bf16* __restrict__ Bhi, const bf16* __restrict__ Blo,
    float* __restrict__ C, int M, int N, int K)
{
    gemm_body(Ahi, Alo, Bhi, Blo, C, nullptr, nullptr, blockIdx.y*128, blockIdx.x*128, N, K);
}

// ================= persistent tensor-core flash attention (P in registers) =================
#define ST 72
#define TB 9216
#define O_QU 0
#define O_KH (4*TB)
#define O_KL (6*TB)
#define O_VH (8*TB)
#define O_VL (10*TB)
#define O_RH (12*TB)
#define O_RL (14*TB)
#define O_BD (16*TB)
#define BDS 66
#define O_ST (O_BD + 2*64*BDS*4)
#define ATT_SMEM (O_ST + 1024)
#define REDS 66
#define NITEMS 512

__global__ __launch_bounds__(256, 1) void attn_mma_kernel(
    const float* __restrict__ r_w_bias, const float* __restrict__ r_r_bias)
{
    extern __shared__ char smc[];
    const uint32_t sb = smem_to_u32(smc);
    float* bds  = (float*)(smc + O_BD);
    float* mred = (float*)(smc + O_ST);
    float* lred = mred + 64;
    __shared__ int s_item;

    const int tid = threadIdx.x;
    const int w = tid >> 5, lane = tid & 31;
    const int mt = w & 3, jh = w >> 2;
    const int r = lane >> 2, c = lane & 3;
    const int lrow = tid >> 2;
    const int dseg = (tid & 3) * 16;
    const int aro = mt*16, bro = jh*32;
    const int aRow = lane & 15, aColOff = (lane >> 4) << 3;
    const int bRow = lane & 7, bHalf = (lane >> 3) & 1, bBlk = lane >> 4;

    for (;;) {
        __syncthreads();
        if (tid == 0) s_item = atomicAdd(&g_ctr, 1);
        __syncthreads();
        const int item = s_item;
        if (item >= NITEMS) return;

        const int i0 = (15 - (item >> 5)) * 64;
        const int b = (item & 31) >> 4, hh = item & 15;
        const int relbase0 = 960 - i0;
        const int ntiles = i0/64 + 17;
        const size_t headoff = (size_t)hh*DH;

        #define CP_TILE(dstoff, gptr) do { \
            uint32_t _d = sb + (uint32_t)(dstoff) + (uint32_t)(lrow*ST + dseg)*2; \
            const bf16* _s = (gptr) + dseg; \
            CP_ASYNC16(_d, _s); CP_ASYNC16(_d + 16, _s + 8); \
        } while (0)
        #define ISSUE_KV(kt, bufi) do { \
            size_t _row = (size_t)(b*KLEN + (kt)*64 + lrow)*DM + headoff; \
            CP_TILE(O_KH + (bufi)*TB, g_khi + _row); \
            CP_TILE(O_KL + (bufi)*TB, g_klo + _row); \
            CP_TILE(O_VH + (bufi)*TB, g_vhi + _row); \
            CP_TILE(O_VL + (bufi)*TB, g_vlo + _row); \
        } while (0)
        #define ISSUE_RB(band, bufi) do { \
            int _rel = relbase0 + (band)*64 + lrow; \
            _rel = _rel < 0 ? 0 : (_rel > KLEN-1 ? KLEN-1 : _rel); \
            size_t _row = (size_t)_rel*DM + headoff; \
            CP_TILE(O_RH + (bufi)*TB, g_rhi + _row); \
            CP_TILE(O_RL + (bufi)*TB, g_rlo + _row); \
        } while (0)

        ISSUE_RB(0, 0); CP_COMMIT();
        ISSUE_RB(1, 1); ISSUE_KV(0, 0); CP_COMMIT();

        // ---- q prep into smem ----
        {
            const float* qrow = g_q + ((size_t)(b*QLEN + i0 + lrow))*DM + headoff + dseg;
            const float* ub = r_w_bias + headoff + dseg;
            const float* vb = r_r_bias + headoff + dseg;
            bf16* quhi = (bf16*)(smc + O_QU);
            bf16* qulo = (bf16*)(smc + O_QU + TB);
            bf16* qvhi = (bf16*)(smc + O_QU + 2*TB);
            bf16* qvlo = (bf16*)(smc + O_QU + 3*TB);
            #pragma unroll
            for (int p = 0; p < 4; p++) {
                float4 q4 = reinterpret_cast<const float4*>(qrow)[p];
                float4 u4 = reinterpret_cast<const float4*>(ub)[p];
                float4 v4 = reinterpret_cast<const float4*>(vb)[p];
                int dd = dseg + p*4;
                uint32_t h, l;
                split2((q4.x+u4.x)*0.125f, (q4.y+u4.y)*0.125f, h, l);
                *(uint32_t*)&quhi[lrow*ST+dd] = h; *(uint32_t*)&qulo[lrow*ST+dd] = l;
                split2((q4.z+u4.z)*0.125f, (q4.w+u4.w)*0.125f, h, l);
                *(uint32_t*)&quhi[lrow*ST+dd+2] = h; *(uint32_t*)&qulo[lrow*ST+dd+2] = l;
                split2((q4.x+v4.x)*0.125f, (q4.y+v4.y)*0.125f, h, l);
                *(uint32_t*)&qvhi[lrow*ST+dd] = h; *(uint32_t*)&qvlo[lrow*ST+dd] = l;
                split2((q4.z+v4.z)*0.125f, (q4.w+v4.w)*0.125f, h, l);
                *(uint32_t*)&qvhi[lrow*ST+dd+2] = h; *(uint32_t*)&qvlo[lrow*ST+dd+2] = l;
            }
        }
        CP_WAIT1();
        __syncthreads();

        // ---- preload q fragments ----
        uint32_t quh[4][4], qul[4][4], qvh[4][4], qvl[4][4];
        #pragma unroll
        for (int kc = 0; kc < 4; kc++) {
            uint32_t aoff = (uint32_t)((aro + aRow)*ST + kc*16 + aColOff) * 2;
            LDMX4(quh[kc][0], quh[kc][1], quh[kc][2], quh[kc][3], sb + O_QU + aoff);
            LDMX4(qul[kc][0], qul[kc][1], qul[kc][2], qul[kc][3], sb + O_QU + TB + aoff);
            LDMX4(qvh[kc][0], qvh[kc][1], qvh[kc][2], qvh[kc][3], sb + O_QU + 2*TB + aoff);
            LDMX4(qvl[kc][0], qvl[kc][1], qvl[kc][2], qvl[kc][3], sb + O_QU + 3*TB + aoff);
        }

        #define LOADB_NK(BH, BL, kcv, BHbase, BLbase) do { \
            _Pragma("unroll") \
            for (int p = 0; p < 2; p++) { \
                uint32_t boff = (uint32_t)((bro + (2*p + bBlk)*8 + bRow)*ST + (kcv)*16 + bHalf*8) * 2; \
                LDMX4(BH[2*p][0], BH[2*p][1], BH[2*p+1][0], BH[2*p+1][1], (BHbase) + boff); \
                LDMX4(BL[2*p][0], BL[2*p][1], BL[2*p+1][0], BL[2*p+1][1], (BLbase) + boff); \
            } \
        } while (0)

        #define GEMM_NK(ACC, AH, AL, BHbase, BLbase) do { \
            uint32_t bhf[2][4][2], blf[2][4][2]; \
            LOADB_NK(bhf[0], blf[0], 0, BHbase, BLbase); \
            _Pragma("unroll") \
            for (int kc = 0; kc < 4; kc++) { \
                int cur = kc & 1; \
                if (kc < 3) LOADB_NK(bhf[cur^1], blf[cur^1], kc+1, BHbase, BLbase); \
                _Pragma("unroll") \
                for (int nt = 0; nt < 4; nt++) \
                    MMA_BF16(ACC[nt], AH[kc], bhf[cur][nt]); \
                _Pragma("unroll") \
                for (int nt = 0; nt < 4; nt++) \
                    MMA_BF16(ACC[nt], AH[kc], blf[cur][nt]); \
                _Pragma("unroll") \
                for (int nt = 0; nt < 4; nt++) \
                    MMA_BF16(ACC[nt], AL[kc], bhf[cur][nt]); \
            } \
        } while (0)

        #define BD_STORE(bda, bufidx) do { \
            float* bdw = bds + (bufidx) * 64 * BDS; \
            _Pragma("unroll") \
            for (int nt = 0; nt < 4; nt++) { \
                int tc = bro + nt*8 + 2*c; \
                *reinterpret_cast<float2*>(&bdw[(aro+r)*BDS + tc]) = make_float2(bda[nt][0], bda[nt][1]); \
                *reinterpret_cast<float2*>(&bdw[(aro+r+8)*BDS + tc]) = make_float2(bda[nt][2], bda[nt][3]); \
            } \
        } while (0)

        // ---- prologue BD bands 0,1 ----
        {
            float bda[4][4];
            #pragma unroll
            for (int nt = 0; nt < 4; nt++)
                #pragma unroll
                for (int q = 0; q < 4; q++) bda[nt][q] = 0.f;
            GEMM_NK(bda, qvh, qvl, sb + O_RH, sb + O_RL);
            BD_STORE(bda, 0);
        }
        __syncthreads();
        ISSUE_RB(2, 0); CP_COMMIT();
        CP_WAIT1();
        __syncthreads();
        {
            float bda[4][4];
            #pragma unroll
            for (int nt = 0; nt < 4; nt++)
                #pragma unroll
                for (int q = 0; q < 4; q++) bda[nt][q] = 0.f;
            GEMM_NK(bda, qvh, qvl, sb + O_RH + TB, sb + O_RL + TB);
            BD_STORE(bda, 1);
        }

        float out[8][4];
        #pragma unroll
        for (int nt = 0; nt < 8; nt++)
            #pragma unroll
            for (int q = 0; q < 4; q++) out[nt][q] = 0.f;
        float lsum0 = 0.f, lsum1 = 0.f, mrun0 = -1e4f, mrun1 = -1e4f;

        for (int kt = 0; kt < ntiles; kt++) {
            const int buf = kt & 1, nbuf = buf ^ 1;
            CP_WAIT0();
            __syncthreads();
            if (kt + 1 < ntiles) {
                ISSUE_KV(kt + 1, nbuf);
                ISSUE_RB(kt + 3, nbuf);
                CP_COMMIT();
            }

            // ---- AC ----
            float s[4][4];
            #pragma unroll
            for (int nt = 0; nt < 4; nt++)
                #pragma unroll
                for (int q = 0; q < 4; q++) s[nt][q] = 0.f;
            GEMM_NK(s, quh, qul, sb + O_KH + buf*TB, sb + O_KL + buf*TB);

            // ---- BD gather (mask hoisted to last tile) ----
            const float* bdLo = bds + buf * 64 * BDS;
            const float* bdHi = bds + nbuf * 64 * BDS;
            #pragma unroll
            for (int nt = 0; nt < 4; nt++)
                #pragma unroll
                for (int q = 0; q < 4; q++) {
                    int il = aro + r + ((q >= 2) ? 8 : 0);
                    int jl = bro + nt*8 + 2*c + (q & 1);
                    int t = jl - il + 63;
                    float bd = (t < 64) ? bdLo[il*BDS + t] : bdHi[il*BDS + t - 64];
                    s[nt][q] += bd;
                }
            if (kt == ntiles - 1) {
                #pragma unroll
                for (int nt = 0; nt < 4; nt++)
                    #pragma unroll
                    for (int q = 0; q < 4; q++) {
                        int il = aro + r + ((q >= 2) ? 8 : 0);
                        int jl = bro + nt*8 + 2*c + (q & 1);
                        if (jl > il) s[nt][q] = -1e30f;
                    }
            }

            // ---- pair barrier + next BD band ----
            if (kt + 1 < ntiles) {
                asm volatile("bar.sync %0, 64;" :: "r"(1 + mt) : "memory");
                float bda[4][4];
                #pragma unroll
                for (int nt = 0; nt < 4; nt++)
                    #pragma unroll
                    for (int q = 0; q < 4; q++) bda[nt][q] = 0.f;
                GEMM_NK(bda, qvh, qvl, sb + O_RH + buf*TB, sb + O_RL + buf*TB);
                BD_STORE(bda, buf);
            }

            // ---- per-half online softmax ----
            float pmax0 = -1e30f, pmax1 = -1e30f;
            #pragma unroll
            for (int nt = 0; nt < 4; nt++) {
                pmax0 = fmaxf(pmax0, fmaxf(s[nt][0], s[nt][1]));
                pmax1 = fmaxf(pmax1, fmaxf(s[nt][2], s[nt][3]));
            }
            pmax0 = fmaxf(pmax0, __shfl_xor_sync(~0u, pmax0, 1));
            pmax0 = fmaxf(pmax0, __shfl_xor_sync(~0u, pmax0, 2));
            pmax1 = fmaxf(pmax1, __shfl_xor_sync(~0u, pmax1, 1));
            pmax1 = fmaxf(pmax1, __shfl_xor_sync(~0u, pmax1, 2));
            float mn0 = fmaxf(mrun0, pmax0), mn1 = fmaxf(mrun1, pmax1);
            float ps0 = 0.f, ps1 = 0.f;
            #pragma unroll
            for (int nt = 0; nt < 4; nt++) {
                s[nt][0] = __expf(s[nt][0] - mn0);
                s[nt][1] = __expf(s[nt][1] - mn0);
                s[nt][2] = __expf(s[nt][2] - mn1);
                s[nt][3] = __expf(s[nt][3] - mn1);
                ps0 += s[nt][0] + s[nt][1];
                ps1 += s[nt][2] + s[nt][3];
            }
            ps0 += __shfl_xor_sync(~0u, ps0, 1); ps0 += __shfl_xor_sync(~0u, ps0, 2);
            ps1 += __shfl_xor_sync(~0u, ps1, 1); ps1 += __shfl_xor_sync(~0u, ps1, 2);
            float corr0 = __expf(mrun0 - mn0), corr1 = __expf(mrun1 - mn1);
            lsum0 = lsum0 * corr0 + ps0;
            lsum1 = lsum1 * corr1 + ps1;
            mrun0 = mn0; mrun1 = mn1;
            #pragma unroll
            for (int nt = 0; nt < 8; nt++) {
                out[nt][0] *= corr0; out[nt][1] *= corr0;
                out[nt][2] *= corr1; out[nt][3] *= corr1;
            }

            // ---- pack P A-frags ----
            uint32_t pah[2][4], pal[2][4];
            #pragma unroll
            for (int kc = 0; kc < 2; kc++) {
                split2(s[2*kc][0],   s[2*kc][1],   pah[kc][0], pal[kc][0]);
                split2(s[2*kc][2],   s[2*kc][3],   pah[kc][1], pal[kc][1]);
                split2(s[2*kc+1][0], s[2*kc+1][1], pah[kc][2], pal[kc][2]);
                split2(s[2*kc+1][2], s[2*kc+1][3], pah[kc][3], pal[kc][3]);
            }

            // ---- PV ----
            {
                uint32_t VH = sb + O_VH + buf*TB, VL = sb + O_VL + buf*TB;
                uint32_t vhf[2][8][2], vlf[2][8][2];
                #define LOADV(slot, kcv) do { \
                    int co = jh*32 + (kcv)*16; \
                    _Pragma("unroll") \
                    for (int p = 0; p < 4; p++) { \
                        uint32_t boff = (uint32_t)((co + bRow + bHalf*8)*ST + (2*p + bBlk)*8) * 2; \
                        LDMX4T(vhf[slot][2*p][0], vhf[slot][2*p][1], vhf[slot][2*p+1][0], vhf[slot][2*p+1][1], VH + boff); \
                        LDMX4T(vlf[slot][2*p][0], vlf[slot][2*p][1], vlf[slot][2*p+1][0], vlf[slot][2*p+1][1], VL + boff); \
                    } \
                } while (0)
                LOADV(0, 0);
                #pragma unroll
                for (int kc = 0; kc < 2; kc++) {
                    if (kc == 0) LOADV(1, 1);
                    #pragma unroll
                    for (int nt = 0; nt < 8; nt++)
                        MMA_BF16(out[nt], pah[kc], vhf[kc][nt]);
                    #pragma unroll
                    for (int nt = 0; nt < 8; nt++)
                        MMA_BF16(out[nt], pah[kc], vlf[kc][nt]);
                    #pragma unroll
                    for (int nt = 0; nt < 8; nt++)
                        MMA_BF16(out[nt], pal[kc], vhf[kc][nt]);
                }
                #undef LOADV
            }
        }

        // ---- combine jh halves ----
        float* red = bds;
        __syncthreads();
        if (jh == 0) {
            #pragma unroll
            for (int nt = 0; nt < 8; nt++) {
                int col = nt*8 + 2*c;
                *reinterpret_cast<float2*>(&red[(aro+r)*REDS + col])   = make_float2(out[nt][0], out[nt][1]);
                *reinterpret_cast<float2*>(&red[(aro+r+8)*REDS + col]) = make_float2(out[nt][2], out[nt][3]);
            }
            if (c == 0) {
                mred[aro+r] = mrun0;   mred[aro+r+8] = mrun1;
                lred[aro+r] = lsum0;   lred[aro+r+8] = lsum1;
            }
        }
        __syncthreads();
        if (jh == 1) {
            float mA0 = mred[aro+r],   lA0 = lred[aro+r];
            float mA1 = mred[aro+r+8], lA1 = lred[aro+r+8];
            float M0 = fmaxf(mA0, mrun0), M1 = fmaxf(mA1, mrun1);
            float eA0 = __expf(mA0 - M0), eB0 = __expf(mrun0 - M0);
            float eA1 = __expf(mA1 - M1), eB1 = __expf(mrun1 - M1);
            float inv0 = 1.f / (lA0*eA0 + lsum0*eB0);
            float inv1 = 1.f / (lA1*eA1 + lsum1*eB1);
            #pragma unroll
            for (int nt = 0; nt < 8; nt++) {
                int col = nt*8 + 2*c;
                float2 oA0 = *reinterpret_cast<float2*>(&red[(aro+r)*REDS + col]);
                float2 oA1 = *reinterpret_cast<float2*>(&red[(aro+r+8)*REDS + col]);
                float v0 = (oA0.x*eA0 + out[nt][0]*eB0) * inv0;
                float v1 = (oA0.y*eA0 + out[nt][1]*eB0) * inv0;
                float v2 = (oA1.x*eA1 + out[nt][2]*eB1) * inv1;
                float v3 = (oA1.y*eA1 + out[nt][3]*eB1) * inv1;
                size_t row0 = (size_t)(b*QLEN + i0 + aro + r) * DM + hh*DH + col;
                size_t row1 = row0 + 8*DM;
                uint32_t h, l;
                split2(v0, v1, h, l);
                *(uint32_t*)&g_avhi[row0] = h; *(uint32_t*)&g_avlo[row0] = l;
                split2(v2, v3, h, l);
                *(uint32_t*)&g_avhi[row1] = h; *(uint32_t*)&g_avlo[row1] = l;
            }
        }
    }
}

// ---------------- launch ----------------
extern "C" void kernel_launch(void* const* d_in, const int* in_sizes, int n_in,
                              void* d_out, int out_size)
{
    (void)in_sizes; (void)n_in; (void)out_size;
    const float* x   = (const float*)d_in[0];
    const float* mem = (const float*)d_in[1];
    const float* pos = (const float*)d_in[2];
    const float* Wq  = (const float*)d_in[4];
    const float* Wk  = (const float*)d_in[5];
    const float* Wv  = (const float*)d_in[6];
    const float* Wr  = (const float*)d_in[7];
    const float* Wo  = (const float*)d_in[8];
    const float* rwb = (const float*)d_in[9];
    const float* rrb = (const float*)d_in[10];
    float* out = (float*)d_out;

    bf16 *pwh, *pwl, *pavh, *pavl;
    cudaGetSymbolAddress((void**)&pwh,  g_whi);
    cudaGetSymbolAddress((void**)&pwl,  g_wlo);
    cudaGetSymbolAddress((void**)&pavh, g_avhi);
    cudaGetSymbolAddress((void**)&pavl, g_avlo);

    prep_all<<<(PREP_TOT + 255)/256, 256>>>(x, mem, pos, Wq, Wk, Wv, Wr, Wo);

    cudaFuncSetAttribute(gemm_proj4, cudaFuncAttributeMaxDynamicSharedMemorySize, GEMM_SMEMB);
    gemm_proj4<<<304, 256, GEMM_SMEMB>>>();

    cudaFuncSetAttribute(attn_mma_kernel, cudaFuncAttributeMaxDynamicSharedMemorySize, ATT_SMEM);
    attn_mma_kernel<<<152, 256, ATT_SMEM>>>(rwb, rrb);

    cudaFuncSetAttribute(gemm_out, cudaFuncAttributeMaxDynamicSharedMemorySize, GEMM_SMEMB);
    gemm_out<<<dim3(DM/128, BSZ*QLEN/128), 256, GEMM_SMEMB>>>(pavh, pavl, pwh+4*DM*DM, pwl+4*DM*DM, out, BSZ*QLEN, DM, DM);
}